// round 11
// baseline (speedup 1.0000x reference)
#include <cuda_runtime.h>
#include <cuda_fp16.h>
#include <cstdint>

#define MROWS 4096
#define NDIM  4096
#define MDIM  4096
#define NIDX  (MDIM * (NDIM / 8))

// ---------------- GEMM tiling ----------------
#define BM 128
#define BN 128
#define BK 64
#define STAGES 3
#define NKCHUNK (NDIM / BK)          // 64

#define ROWB      144                // 128B data + 16B pad
#define ARR_BYTES (128 * ROWB)       // 18432
#define STAGE_BYTES (2 * ARR_BYTES)  // 36864
#define SMEM_TOTAL (STAGES * STAGE_BYTES)   // 110592

// FWHT smem skews
#define SKEW8(i)  ((i) + ((i) >> 3))    // for radix-8 (fwht_in), max 4606
#define SKEW16(i) ((i) + ((i) >> 4))    // for radix-16 (fwht_out), max 4351

// Scratch (allocation-free rule)
__device__ __half g_X[(size_t)MROWS * NDIM];
__device__ __half g_W[(size_t)MDIM * NDIM];
__device__ __half g_C[(size_t)MROWS * MDIM];   // fp16 GEMM output

// ---------------- PTX helpers ----------------
__device__ __forceinline__ uint32_t smem_u32(const void* p) {
    uint32_t a;
    asm("{ .reg .u64 t; cvta.to.shared.u64 t, %1; cvt.u32.u64 %0, t; }" : "=r"(a) : "l"(p));
    return a;
}
__device__ __forceinline__ void cp_async16(uint32_t dst, const void* src) {
    asm volatile("cp.async.cg.shared.global [%0], [%1], 16;" :: "r"(dst), "l"(src));
}
__device__ __forceinline__ void cp_commit() {
    asm volatile("cp.async.commit_group;" ::: "memory");
}
template<int N> __device__ __forceinline__ void cp_wait() {
    asm volatile("cp.async.wait_group %0;" :: "n"(N) : "memory");
}
__device__ __forceinline__ void ldm_x4(uint32_t* r, uint32_t addr) {
    asm volatile("ldmatrix.sync.aligned.m8n8.x4.shared.b16 {%0,%1,%2,%3}, [%4];"
                 : "=r"(r[0]), "=r"(r[1]), "=r"(r[2]), "=r"(r[3]) : "r"(addr));
}
__device__ __forceinline__ void mma_f16(float* c, const uint32_t* a, uint32_t b0, uint32_t b1) {
    asm volatile(
        "mma.sync.aligned.m16n8k16.row.col.f32.f16.f16.f32 "
        "{%0,%1,%2,%3}, {%4,%5,%6,%7}, {%8,%9}, {%0,%1,%2,%3};"
        : "+f"(c[0]), "+f"(c[1]), "+f"(c[2]), "+f"(c[3])
        : "r"(a[0]), "r"(a[1]), "r"(a[2]), "r"(a[3]), "r"(b0), "r"(b1));
}

// radix-8 butterfly: stages h, 2h, 4h on 8 h-strided values
__device__ __forceinline__ void radix8(float* v) {
    float t0 = v[0] + v[1], t1 = v[0] - v[1];
    float t2 = v[2] + v[3], t3 = v[2] - v[3];
    float t4 = v[4] + v[5], t5 = v[4] - v[5];
    float t6 = v[6] + v[7], t7 = v[6] - v[7];
    float u0 = t0 + t2, u2 = t0 - t2, u1 = t1 + t3, u3 = t1 - t3;
    float u4 = t4 + t6, u6 = t4 - t6, u5 = t5 + t7, u7 = t5 - t7;
    v[0] = u0 + u4; v[4] = u0 - u4;
    v[1] = u1 + u5; v[5] = u1 - u5;
    v[2] = u2 + u6; v[6] = u2 - u6;
    v[3] = u3 + u7; v[7] = u3 - u7;
}

// radix-16: stages h,2h,4h,8h on 16 h-strided values (two radix-8 + combine)
__device__ __forceinline__ void radix16(float* v) {
    radix8(v);
    radix8(v + 8);
    #pragma unroll
    for (int k = 0; k < 8; k++) {
        float a = v[k], b = v[k + 8];
        v[k] = a + b;
        v[k + 8] = a - b;
    }
}

// ---------------------------------------------------------------------------
// Kernel 1 (merged prep): blocks [0,4096): fwht_in rows; [4096,8192): dequant rows
// 512 threads per block.
// ---------------------------------------------------------------------------
__global__ __launch_bounds__(512)
void k_prep(const float* __restrict__ in,
            const float* __restrict__ SU,
            const float* __restrict__ grid,
            const int*   __restrict__ qidxs)
{
    __shared__ float s[4608];            // SKEW8 space
    const int t = threadIdx.x;

    if (blockIdx.x >= MROWS) {
        // ---- dequant: one W row per block, one codeword per thread ----
        const int row = blockIdx.x - MROWS;
        const int idx = qidxs[row * 512 + t];
        const float4* g = (const float4*)(grid + (size_t)idx * 8);
        float4 a = g[0], b = g[1];
        __half h[8];
        h[0] = __float2half(a.x); h[1] = __float2half(a.y);
        h[2] = __float2half(a.z); h[3] = __float2half(a.w);
        h[4] = __float2half(b.x); h[5] = __float2half(b.y);
        h[6] = __float2half(b.z); h[7] = __float2half(b.w);
        *(uint4*)(g_W + (size_t)row * NDIM + t * 8) = *(uint4*)h;
        return;
    }

    // ---- fwht_in: radix-8, 8 elts/thread ----
    const int row = blockIdx.x;
    {
        float v[8];
        const float4* r4 = (const float4*)(in + (size_t)row * NDIM);
        const float4* su4 = (const float4*)SU;
        float4 a = r4[2 * t],     sa = su4[2 * t];
        float4 b = r4[2 * t + 1], sb = su4[2 * t + 1];
        v[0] = a.x * sa.x; v[1] = a.y * sa.y; v[2] = a.z * sa.z; v[3] = a.w * sa.w;
        v[4] = b.x * sb.x; v[5] = b.y * sb.y; v[6] = b.z * sb.z; v[7] = b.w * sb.w;
        radix8(v);
        #pragma unroll
        for (int j = 0; j < 8; j++) s[SKEW8(8 * t + j)] = v[j];
    }
    __syncthreads();

    #pragma unroll
    for (int lh = 3; lh <= 9; lh += 3) {
        const int h = 1 << lh;
        const int i = ((t >> lh) << (lh + 3)) | (t & (h - 1));
        float v[8];
        #pragma unroll
        for (int k = 0; k < 8; k++) v[k] = s[SKEW8(i + k * h)];
        radix8(v);
        #pragma unroll
        for (int k = 0; k < 8; k++) s[SKEW8(i + k * h)] = v[k];
        __syncthreads();
    }

    {
        __half h8[8];
        #pragma unroll
        for (int j = 0; j < 8; j++)
            h8[j] = __float2half(s[SKEW8(8 * t + j)] * 0.015625f);
        *(uint4*)(g_X + (size_t)row * NDIM + 8 * t) = *(uint4*)h8;
    }
}

// ---------------------------------------------------------------------------
// Kernel 3: fp16 HMMA GEMM  C[M,N] = X[M,K] * W[N,K]^T  (fp16 out) — unchanged
// ---------------------------------------------------------------------------
__device__ __forceinline__ void issue_stage_loads(
    uint32_t sb, int buf, int c, int tid,
    const __half* A, const __half* B)
{
    const int k0 = c * BK;
    const uint32_t stage = sb + buf * STAGE_BYTES;
    #pragma unroll
    for (int it = 0; it < 4; it++) {
        int idx = tid + it * 256;
        int r = idx >> 3;
        int cb = idx & 7;
        cp_async16(stage + r * ROWB + cb * 16,
                   A + (size_t)r * NDIM + k0 + cb * 8);
    }
    #pragma unroll
    for (int it = 0; it < 4; it++) {
        int idx = tid + it * 256;
        int r = idx >> 3;
        int cb = idx & 7;
        cp_async16(stage + ARR_BYTES + r * ROWB + cb * 16,
                   B + (size_t)r * NDIM + k0 + cb * 8);
    }
}

__global__ __launch_bounds__(256, 2)
void k_gemm_hmma()
{
    extern __shared__ char smem[];
    const uint32_t sb = smem_u32(smem);
    const int tid = threadIdx.x;
    const int wid = tid >> 5, lane = tid & 31;
    const int wm = wid & 1;
    const int wn = wid >> 1;

    const __half* A = g_X + (size_t)blockIdx.y * BM * NDIM;
    const __half* B = g_W + (size_t)blockIdx.x * BN * NDIM;

    float acc[4][4][4];
    #pragma unroll
    for (int i = 0; i < 4; i++)
        #pragma unroll
        for (int j = 0; j < 4; j++)
            #pragma unroll
            for (int e = 0; e < 4; e++) acc[i][j][e] = 0.f;

    issue_stage_loads(sb, 0, 0, tid, A, B); cp_commit();
    issue_stage_loads(sb, 1, 1, tid, A, B); cp_commit();

    const int lrow = lane & 15;
    const int lkb  = (lane >> 4) * 16;

    for (int c = 0; c < NKCHUNK; c++) {
        cp_wait<1>();
        __syncthreads();

        if (c + 2 < NKCHUNK) {
            int nb = (c + 2) % STAGES;
            issue_stage_loads(sb, nb, c + 2, tid, A, B);
        }
        cp_commit();

        const uint32_t stage = sb + (c % STAGES) * STAGE_BYTES;
        const uint32_t sA = stage;
        const uint32_t sB = stage + ARR_BYTES;

        #pragma unroll
        for (int kk = 0; kk < 4; kk++) {
            const int kb = kk * 32 + lkb;
            uint32_t af[4][4], bf[2][4];
            #pragma unroll
            for (int i = 0; i < 4; i++)
                ldm_x4(af[i], sA + (wm * 64 + i * 16 + lrow) * ROWB + kb);
            #pragma unroll
            for (int bt = 0; bt < 2; bt++)
                ldm_x4(bf[bt], sB + (wn * 32 + bt * 16 + lrow) * ROWB + kb);
            #pragma unroll
            for (int i = 0; i < 4; i++)
                #pragma unroll
                for (int j = 0; j < 4; j++) {
                    const int bt = j >> 1, odd = j & 1;
                    mma_f16(acc[i][j], af[i], bf[bt][odd], bf[bt][odd + 2]);
                }
        }
    }

    // Epilogue: fp16 stores into g_C
    const int crow0 = blockIdx.y * BM + wm * 64 + (lane >> 2);
    const int ccol0 = blockIdx.x * BN + wn * 32 + (lane & 3) * 2;
    #pragma unroll
    for (int i = 0; i < 4; i++)
        #pragma unroll
        for (int j = 0; j < 4; j++) {
            __half2 h0 = __floats2half2_rn(acc[i][j][0], acc[i][j][1]);
            __half2 h1 = __floats2half2_rn(acc[i][j][2], acc[i][j][3]);
            *(__half2*)(g_C + (size_t)(crow0 + i * 16)     * MDIM + ccol0 + j * 8) = h0;
            *(__half2*)(g_C + (size_t)(crow0 + i * 16 + 8) * MDIM + ccol0 + j * 8) = h1;
        }
}

// ---------------------------------------------------------------------------
// Kernel 4: out = fwht(g_C)/64 * SV  (radix-16, 256 thr x 16 elts)
// ---------------------------------------------------------------------------
__global__ __launch_bounds__(256)
void k_fwht_out(float* __restrict__ out,
                const float* __restrict__ SV)
{
    __shared__ float s[4352];            // SKEW16 space
    const int row = blockIdx.x;
    const int t = threadIdx.x;

    // load 16 contiguous fp16 + stages h=1..8 in registers
    {
        float v[16];
        const uint4* c4 = (const uint4*)(g_C + (size_t)row * MDIM);
        #pragma unroll
        for (int p = 0; p < 2; p++) {
            uint4 u = c4[2 * t + p];
            float2 f0 = __half22float2(*(__half2*)&u.x);
            float2 f1 = __half22float2(*(__half2*)&u.y);
            float2 f2 = __half22float2(*(__half2*)&u.z);
            float2 f3 = __half22float2(*(__half2*)&u.w);
            v[8 * p + 0] = f0.x; v[8 * p + 1] = f0.y;
            v[8 * p + 2] = f1.x; v[8 * p + 3] = f1.y;
            v[8 * p + 4] = f2.x; v[8 * p + 5] = f2.y;
            v[8 * p + 6] = f3.x; v[8 * p + 7] = f3.y;
        }
        radix16(v);
        #pragma unroll
        for (int j = 0; j < 16; j++) s[SKEW16(16 * t + j)] = v[j];
    }
    __syncthreads();

    // 2 radix-16 smem passes: h = 16, 256
    #pragma unroll
    for (int lh = 4; lh <= 8; lh += 4) {
        const int h = 1 << lh;
        const int i = ((t >> lh) << (lh + 4)) | (t & (h - 1));
        float v[16];
        #pragma unroll
        for (int k = 0; k < 16; k++) v[k] = s[SKEW16(i + k * h)];
        radix16(v);
        #pragma unroll
        for (int k = 0; k < 16; k++) s[SKEW16(i + k * h)] = v[k];
        __syncthreads();
    }

    // scale by 1/64 * SV, write fp32
    {
        const float4* sv4 = (const float4*)SV;
        float4* out4 = (float4*)(out + (size_t)row * MDIM);
        #pragma unroll
        for (int p = 0; p < 4; p++) {
            float4 sv = sv4[4 * t + p];
            float4 o;
            o.x = s[SKEW16(16 * t + 4 * p + 0)] * 0.015625f * sv.x;
            o.y = s[SKEW16(16 * t + 4 * p + 1)] * 0.015625f * sv.y;
            o.z = s[SKEW16(16 * t + 4 * p + 2)] * 0.015625f * sv.z;
            o.w = s[SKEW16(16 * t + 4 * p + 3)] * 0.015625f * sv.w;
            out4[4 * t + p] = o;
        }
    }
}

// ---------------------------------------------------------------------------
extern "C" void kernel_launch(void* const* d_in, const int* in_sizes, int n_in,
                              void* d_out, int out_size)
{
    const float* input = (const float*)d_in[0];
    const float* SU    = (const float*)d_in[1];
    const float* SV    = (const float*)d_in[2];
    const float* grid  = (const float*)d_in[3];
    const int*   qidx  = (const int*)  d_in[4];
    float* out = (float*)d_out;
    (void)in_sizes; (void)n_in; (void)out_size;

    cudaFuncSetAttribute(k_gemm_hmma, cudaFuncAttributeMaxDynamicSharedMemorySize, SMEM_TOTAL);

    k_prep<<<2 * MROWS, 512>>>(input, SU, grid, qidx);
    {
        dim3 gd(MDIM / BN, MROWS / BM);
        k_gemm_hmma<<<gd, 256, SMEM_TOTAL>>>();
    }
    k_fwht_out<<<MROWS, 256>>>(out, SV);
}

// round 12
// speedup vs baseline: 1.1435x; 1.1435x over previous
#include <cuda_runtime.h>
#include <cuda_fp16.h>
#include <cstdint>

#define MROWS 4096
#define NDIM  4096
#define MDIM  4096
#define NIDX  (MDIM * (NDIM / 8))

// ---------------- GEMM tiling ----------------
#define BM 128
#define BN 128
#define BK 64
#define STAGES 3
#define NKCHUNK (NDIM / BK)          // 64

#define ROWB      144                // 128B data + 16B pad
#define ARR_BYTES (128 * ROWB)       // 18432
#define STAGE_BYTES (2 * ARR_BYTES)  // 36864
#define SMEM_TOTAL (STAGES * STAGE_BYTES)   // 110592

// FWHT smem skew: phys(i) = i + (i>>3); max phys(4095) = 4606
#define FW_SMEM 4608
#define SKEW(i) ((i) + ((i) >> 3))

// Scratch (allocation-free rule)
__device__ __half g_X[(size_t)MROWS * NDIM];
__device__ __half g_W[(size_t)MDIM * NDIM];
__device__ __half g_C[(size_t)MROWS * MDIM];   // fp16 GEMM output

// ---------------- PTX helpers ----------------
__device__ __forceinline__ uint32_t smem_u32(const void* p) {
    uint32_t a;
    asm("{ .reg .u64 t; cvta.to.shared.u64 t, %1; cvt.u32.u64 %0, t; }" : "=r"(a) : "l"(p));
    return a;
}
__device__ __forceinline__ void cp_async16(uint32_t dst, const void* src) {
    asm volatile("cp.async.cg.shared.global [%0], [%1], 16;" :: "r"(dst), "l"(src));
}
__device__ __forceinline__ void cp_commit() {
    asm volatile("cp.async.commit_group;" ::: "memory");
}
template<int N> __device__ __forceinline__ void cp_wait() {
    asm volatile("cp.async.wait_group %0;" :: "n"(N) : "memory");
}
__device__ __forceinline__ void ldm_x4(uint32_t* r, uint32_t addr) {
    asm volatile("ldmatrix.sync.aligned.m8n8.x4.shared.b16 {%0,%1,%2,%3}, [%4];"
                 : "=r"(r[0]), "=r"(r[1]), "=r"(r[2]), "=r"(r[3]) : "r"(addr));
}
__device__ __forceinline__ void mma_f16(float* c, const uint32_t* a, uint32_t b0, uint32_t b1) {
    asm volatile(
        "mma.sync.aligned.m16n8k16.row.col.f32.f16.f16.f32 "
        "{%0,%1,%2,%3}, {%4,%5,%6,%7}, {%8,%9}, {%0,%1,%2,%3};"
        : "+f"(c[0]), "+f"(c[1]), "+f"(c[2]), "+f"(c[3])
        : "r"(a[0]), "r"(a[1]), "r"(a[2]), "r"(a[3]), "r"(b0), "r"(b1));
}

// radix-8 butterfly: stages h, 2h, 4h on 8 h-strided values
__device__ __forceinline__ void radix8(float* v) {
    float t0 = v[0] + v[1], t1 = v[0] - v[1];
    float t2 = v[2] + v[3], t3 = v[2] - v[3];
    float t4 = v[4] + v[5], t5 = v[4] - v[5];
    float t6 = v[6] + v[7], t7 = v[6] - v[7];
    float u0 = t0 + t2, u2 = t0 - t2, u1 = t1 + t3, u3 = t1 - t3;
    float u4 = t4 + t6, u6 = t4 - t6, u5 = t5 + t7, u7 = t5 - t7;
    v[0] = u0 + u4; v[4] = u0 - u4;
    v[1] = u1 + u5; v[5] = u1 - u5;
    v[2] = u2 + u6; v[6] = u2 - u6;
    v[3] = u3 + u7; v[7] = u3 - u7;
}

// ---------------------------------------------------------------------------
// Kernel 1: dequantize W -> fp16
// ---------------------------------------------------------------------------
__global__ __launch_bounds__(256)
void k_dequant(const float* __restrict__ grid,
               const int*   __restrict__ qidxs)
{
    int t = blockIdx.x * blockDim.x + threadIdx.x;
    if (t >= NIDX) return;
    int idx = qidxs[t];
    const float4* g = (const float4*)(grid + (size_t)idx * 8);
    float4 a = g[0], b = g[1];
    __half h[8];
    h[0] = __float2half(a.x); h[1] = __float2half(a.y);
    h[2] = __float2half(a.z); h[3] = __float2half(a.w);
    h[4] = __float2half(b.x); h[5] = __float2half(b.y);
    h[6] = __float2half(b.z); h[7] = __float2half(b.w);
    *(uint4*)(g_W + (size_t)t * 8) = *(uint4*)h;
}

// ---------------------------------------------------------------------------
// Kernel 2: X = fwht(input * SU)/64 -> fp16   (radix-8, strength-reduced skew)
// ---------------------------------------------------------------------------
__global__ __launch_bounds__(512)
void k_fwht_in(const float* __restrict__ in,
               const float* __restrict__ SU)
{
    __shared__ float s[FW_SMEM];
    const int row = blockIdx.x;
    const int t = threadIdx.x;
    const int pb0 = 9 * t;               // phys base for contiguous 8

    // load 8 contiguous + SU scale + stages h=1,2,4 in registers
    {
        float v[8];
        const float4* r4 = (const float4*)(in + (size_t)row * NDIM);
        const float4* su4 = (const float4*)SU;
        float4 a = r4[2 * t],     sa = su4[2 * t];
        float4 b = r4[2 * t + 1], sb = su4[2 * t + 1];
        v[0] = a.x * sa.x; v[1] = a.y * sa.y; v[2] = a.z * sa.z; v[3] = a.w * sa.w;
        v[4] = b.x * sb.x; v[5] = b.y * sb.y; v[6] = b.z * sb.z; v[7] = b.w * sb.w;
        radix8(v);
        #pragma unroll
        for (int j = 0; j < 8; j++) s[pb0 + j] = v[j];
    }
    __syncthreads();

    // 3 radix-8 smem passes: h = 8, 64, 512; phys stride = 9h/8 (exact, no carry)
    #pragma unroll
    for (int lh = 3; lh <= 9; lh += 3) {
        const int h = 1 << lh;
        const int i = ((t >> lh) << (lh + 3)) | (t & (h - 1));
        const int pb = SKEW(i);
        const int st = 9 << (lh - 3);    // 9, 72, 576
        float v[8];
        #pragma unroll
        for (int k = 0; k < 8; k++) v[k] = s[pb + st * k];
        radix8(v);
        #pragma unroll
        for (int k = 0; k < 8; k++) s[pb + st * k] = v[k];
        __syncthreads();
    }

    // store fp16 (8 contiguous per thread)
    {
        __half h8[8];
        #pragma unroll
        for (int j = 0; j < 8; j++)
            h8[j] = __float2half(s[pb0 + j] * 0.015625f);
        *(uint4*)(g_X + (size_t)row * NDIM + 8 * t) = *(uint4*)h8;
    }
}

// ---------------------------------------------------------------------------
// Kernel 3: fp16 HMMA GEMM  C[M,N] = X[M,K] * W[N,K]^T  (fp16 out) — unchanged
// ---------------------------------------------------------------------------
__device__ __forceinline__ void issue_stage_loads(
    uint32_t sb, int buf, int c, int tid,
    const __half* A, const __half* B)
{
    const int k0 = c * BK;
    const uint32_t stage = sb + buf * STAGE_BYTES;
    #pragma unroll
    for (int it = 0; it < 4; it++) {
        int idx = tid + it * 256;        // 0..1023
        int r = idx >> 3;                // 0..127
        int cb = idx & 7;                // 16B chunk within 128B row
        cp_async16(stage + r * ROWB + cb * 16,
                   A + (size_t)r * NDIM + k0 + cb * 8);
    }
    #pragma unroll
    for (int it = 0; it < 4; it++) {
        int idx = tid + it * 256;
        int r = idx >> 3;
        int cb = idx & 7;
        cp_async16(stage + ARR_BYTES + r * ROWB + cb * 16,
                   B + (size_t)r * NDIM + k0 + cb * 8);
    }
}

__global__ __launch_bounds__(256, 2)
void k_gemm_hmma()
{
    extern __shared__ char smem[];
    const uint32_t sb = smem_u32(smem);
    const int tid = threadIdx.x;
    const int wid = tid >> 5, lane = tid & 31;
    const int wm = wid & 1;          // 0..1 (M)
    const int wn = wid >> 1;         // 0..3 (N)

    const __half* A = g_X + (size_t)blockIdx.y * BM * NDIM;
    const __half* B = g_W + (size_t)blockIdx.x * BN * NDIM;

    float acc[4][4][4];
    #pragma unroll
    for (int i = 0; i < 4; i++)
        #pragma unroll
        for (int j = 0; j < 4; j++)
            #pragma unroll
            for (int e = 0; e < 4; e++) acc[i][j][e] = 0.f;

    issue_stage_loads(sb, 0, 0, tid, A, B); cp_commit();
    issue_stage_loads(sb, 1, 1, tid, A, B); cp_commit();

    const int lrow = lane & 15;
    const int lkb  = (lane >> 4) * 16;

    for (int c = 0; c < NKCHUNK; c++) {
        cp_wait<1>();
        __syncthreads();

        if (c + 2 < NKCHUNK) {
            int nb = (c + 2) % STAGES;
            issue_stage_loads(sb, nb, c + 2, tid, A, B);
        }
        cp_commit();

        const uint32_t stage = sb + (c % STAGES) * STAGE_BYTES;
        const uint32_t sA = stage;
        const uint32_t sB = stage + ARR_BYTES;

        #pragma unroll
        for (int kk = 0; kk < 4; kk++) {
            const int kb = kk * 32 + lkb;
            uint32_t af[4][4], bf[2][4];
            #pragma unroll
            for (int i = 0; i < 4; i++)
                ldm_x4(af[i], sA + (wm * 64 + i * 16 + lrow) * ROWB + kb);
            #pragma unroll
            for (int bt = 0; bt < 2; bt++)
                ldm_x4(bf[bt], sB + (wn * 32 + bt * 16 + lrow) * ROWB + kb);
            #pragma unroll
            for (int i = 0; i < 4; i++)
                #pragma unroll
                for (int j = 0; j < 4; j++) {
                    const int bt = j >> 1, odd = j & 1;
                    mma_f16(acc[i][j], af[i], bf[bt][odd], bf[bt][odd + 2]);
                }
        }
    }

    // Epilogue: fp16 stores into g_C
    const int crow0 = blockIdx.y * BM + wm * 64 + (lane >> 2);
    const int ccol0 = blockIdx.x * BN + wn * 32 + (lane & 3) * 2;
    #pragma unroll
    for (int i = 0; i < 4; i++)
        #pragma unroll
        for (int j = 0; j < 4; j++) {
            __half2 h0 = __floats2half2_rn(acc[i][j][0], acc[i][j][1]);
            __half2 h1 = __floats2half2_rn(acc[i][j][2], acc[i][j][3]);
            *(__half2*)(g_C + (size_t)(crow0 + i * 16)     * MDIM + ccol0 + j * 8) = h0;
            *(__half2*)(g_C + (size_t)(crow0 + i * 16 + 8) * MDIM + ccol0 + j * 8) = h1;
        }
}

// ---------------------------------------------------------------------------
// Kernel 4: out = fwht(g_C)/64 * SV  (radix-8, fp16 in, strength-reduced skew)
// ---------------------------------------------------------------------------
__global__ __launch_bounds__(512)
void k_fwht_out(float* __restrict__ out,
                const float* __restrict__ SV)
{
    __shared__ float s[FW_SMEM];
    const int row = blockIdx.x;
    const int t = threadIdx.x;
    const int pb0 = 9 * t;

    {
        uint4 u = ((const uint4*)(g_C + (size_t)row * MDIM))[t];
        float2 f0 = __half22float2(*(__half2*)&u.x);
        float2 f1 = __half22float2(*(__half2*)&u.y);
        float2 f2 = __half22float2(*(__half2*)&u.z);
        float2 f3 = __half22float2(*(__half2*)&u.w);
        float v[8] = {f0.x, f0.y, f1.x, f1.y, f2.x, f2.y, f3.x, f3.y};
        radix8(v);
        #pragma unroll
        for (int j = 0; j < 8; j++) s[pb0 + j] = v[j];
    }
    __syncthreads();

    #pragma unroll
    for (int lh = 3; lh <= 9; lh += 3) {
        const int h = 1 << lh;
        const int i = ((t >> lh) << (lh + 3)) | (t & (h - 1));
        const int pb = SKEW(i);
        const int st = 9 << (lh - 3);    // 9, 72, 576
        float v[8];
        #pragma unroll
        for (int k = 0; k < 8; k++) v[k] = s[pb + st * k];
        radix8(v);
        #pragma unroll
        for (int k = 0; k < 8; k++) s[pb + st * k] = v[k];
        __syncthreads();
    }

    {
        const float4* sv4 = (const float4*)SV;
        float4 sa = sv4[2 * t], sb = sv4[2 * t + 1];
        float4 o0, o1;
        o0.x = s[pb0 + 0] * 0.015625f * sa.x;
        o0.y = s[pb0 + 1] * 0.015625f * sa.y;
        o0.z = s[pb0 + 2] * 0.015625f * sa.z;
        o0.w = s[pb0 + 3] * 0.015625f * sa.w;
        o1.x = s[pb0 + 4] * 0.015625f * sb.x;
        o1.y = s[pb0 + 5] * 0.015625f * sb.y;
        o1.z = s[pb0 + 6] * 0.015625f * sb.z;
        o1.w = s[pb0 + 7] * 0.015625f * sb.w;
        float4* out4 = (float4*)(out + (size_t)row * MDIM);
        out4[2 * t]     = o0;
        out4[2 * t + 1] = o1;
    }
}

// ---------------------------------------------------------------------------
extern "C" void kernel_launch(void* const* d_in, const int* in_sizes, int n_in,
                              void* d_out, int out_size)
{
    const float* input = (const float*)d_in[0];
    const float* SU    = (const float*)d_in[1];
    const float* SV    = (const float*)d_in[2];
    const float* grid  = (const float*)d_in[3];
    const int*   qidx  = (const int*)  d_in[4];
    float* out = (float*)d_out;
    (void)in_sizes; (void)n_in; (void)out_size;

    cudaFuncSetAttribute(k_gemm_hmma, cudaFuncAttributeMaxDynamicSharedMemorySize, SMEM_TOTAL);

    k_dequant<<<NIDX / 256, 256>>>(grid, qidx);
    k_fwht_in<<<MROWS, 512>>>(input, SU);
    {
        dim3 gd(MDIM / BN, MROWS / BM);
        k_gemm_hmma<<<gd, 256, SMEM_TOTAL>>>();
    }
    k_fwht_out<<<MROWS, 512>>>(out, SV);
}

// round 13
// speedup vs baseline: 1.7914x; 1.5666x over previous
#include <cuda_runtime.h>
#include <cuda_fp16.h>
#include <cstdint>

#define MROWS 4096
#define NDIM  4096
#define MDIM  4096
#define NIDX  (MDIM * (NDIM / 8))

// ---------------- GEMM tiling ----------------
#define BM 128
#define BN 128
#define BK 64
#define STAGES 3
#define NKCHUNK (NDIM / BK)          // 64

#define ROWB      144                // 128B data + 16B pad
#define ARR_BYTES (128 * ROWB)       // 18432
#define STAGE_BYTES (2 * ARR_BYTES)  // 36864
#define SMEM_TOTAL (STAGES * STAGE_BYTES)   // 110592

// FWHT smem skew: phys(i) = i + (i>>3); max phys(4095) = 4606
#define FW_SMEM 4608
#define SKEW(i) ((i) + ((i) >> 3))

// Scratch (allocation-free rule)
__device__ __half g_X[(size_t)MROWS * NDIM];
__device__ __half g_W[(size_t)MDIM * NDIM];
__device__ __half g_C[(size_t)MROWS * MDIM];   // fp16 GEMM output

// ---------------- PTX helpers ----------------
__device__ __forceinline__ uint32_t smem_u32(const void* p) {
    uint32_t a;
    asm("{ .reg .u64 t; cvta.to.shared.u64 t, %1; cvt.u32.u64 %0, t; }" : "=r"(a) : "l"(p));
    return a;
}
__device__ __forceinline__ void cp_async16(uint32_t dst, const void* src) {
    asm volatile("cp.async.cg.shared.global [%0], [%1], 16;" :: "r"(dst), "l"(src));
}
__device__ __forceinline__ void cp_commit() {
    asm volatile("cp.async.commit_group;" ::: "memory");
}
template<int N> __device__ __forceinline__ void cp_wait() {
    asm volatile("cp.async.wait_group %0;" :: "n"(N) : "memory");
}
__device__ __forceinline__ void ldm_x4(uint32_t* r, uint32_t addr) {
    asm volatile("ldmatrix.sync.aligned.m8n8.x4.shared.b16 {%0,%1,%2,%3}, [%4];"
                 : "=r"(r[0]), "=r"(r[1]), "=r"(r[2]), "=r"(r[3]) : "r"(addr));
}
__device__ __forceinline__ void mma_f16(float* c, const uint32_t* a, uint32_t b0, uint32_t b1) {
    asm volatile(
        "mma.sync.aligned.m16n8k16.row.col.f32.f16.f16.f32 "
        "{%0,%1,%2,%3}, {%4,%5,%6,%7}, {%8,%9}, {%0,%1,%2,%3};"
        : "+f"(c[0]), "+f"(c[1]), "+f"(c[2]), "+f"(c[3])
        : "r"(a[0]), "r"(a[1]), "r"(a[2]), "r"(a[3]), "r"(b0), "r"(b1));
}

// radix-8 butterfly: stages h, 2h, 4h on 8 h-strided values
__device__ __forceinline__ void radix8(float* v) {
    float t0 = v[0] + v[1], t1 = v[0] - v[1];
    float t2 = v[2] + v[3], t3 = v[2] - v[3];
    float t4 = v[4] + v[5], t5 = v[4] - v[5];
    float t6 = v[6] + v[7], t7 = v[6] - v[7];
    float u0 = t0 + t2, u2 = t0 - t2, u1 = t1 + t3, u3 = t1 - t3;
    float u4 = t4 + t6, u6 = t4 - t6, u5 = t5 + t7, u7 = t5 - t7;
    v[0] = u0 + u4; v[4] = u0 - u4;
    v[1] = u1 + u5; v[5] = u1 - u5;
    v[2] = u2 + u6; v[6] = u2 - u6;
    v[3] = u3 + u7; v[7] = u3 - u7;
}

// ---------------------------------------------------------------------------
// Kernel 1: dequantize W -> fp16
// ---------------------------------------------------------------------------
__global__ __launch_bounds__(256)
void k_dequant(const float* __restrict__ grid,
               const int*   __restrict__ qidxs)
{
    int t = blockIdx.x * blockDim.x + threadIdx.x;
    if (t >= NIDX) return;
    int idx = qidxs[t];
    const float4* g = (const float4*)(grid + (size_t)idx * 8);
    float4 a = g[0], b = g[1];
    __half h[8];
    h[0] = __float2half(a.x); h[1] = __float2half(a.y);
    h[2] = __float2half(a.z); h[3] = __float2half(a.w);
    h[4] = __float2half(b.x); h[5] = __float2half(b.y);
    h[6] = __float2half(b.z); h[7] = __float2half(b.w);
    *(uint4*)(g_W + (size_t)t * 8) = *(uint4*)h;
}

// ---------------------------------------------------------------------------
// Kernel 2: X = fwht(input * SU)/64 -> fp16   (radix-8, 512 thr, 8 elts/thr)
// ---------------------------------------------------------------------------
__global__ __launch_bounds__(512)
void k_fwht_in(const float* __restrict__ in,
               const float* __restrict__ SU)
{
    __shared__ float s[FW_SMEM];
    const int row = blockIdx.x;
    const int t = threadIdx.x;

    // load 8 contiguous + SU scale + stages h=1,2,4 in registers
    {
        float v[8];
        const float4* r4 = (const float4*)(in + (size_t)row * NDIM);
        const float4* su4 = (const float4*)SU;
        float4 a = r4[2 * t],     sa = su4[2 * t];
        float4 b = r4[2 * t + 1], sb = su4[2 * t + 1];
        v[0] = a.x * sa.x; v[1] = a.y * sa.y; v[2] = a.z * sa.z; v[3] = a.w * sa.w;
        v[4] = b.x * sb.x; v[5] = b.y * sb.y; v[6] = b.z * sb.z; v[7] = b.w * sb.w;
        radix8(v);
        #pragma unroll
        for (int j = 0; j < 8; j++) s[SKEW(8 * t + j)] = v[j];
    }
    __syncthreads();

    // 3 radix-8 smem passes: h = 8, 64, 512
    #pragma unroll
    for (int lh = 3; lh <= 9; lh += 3) {
        const int h = 1 << lh;
        const int i = ((t >> lh) << (lh + 3)) | (t & (h - 1));
        float v[8];
        #pragma unroll
        for (int k = 0; k < 8; k++) v[k] = s[SKEW(i + k * h)];
        radix8(v);
        #pragma unroll
        for (int k = 0; k < 8; k++) s[SKEW(i + k * h)] = v[k];
        __syncthreads();
    }

    // store fp16 (8 contiguous per thread)
    {
        __half h8[8];
        #pragma unroll
        for (int j = 0; j < 8; j++)
            h8[j] = __float2half(s[SKEW(8 * t + j)] * 0.015625f);
        *(uint4*)(g_X + (size_t)row * NDIM + 8 * t) = *(uint4*)h8;
    }
}

// ---------------------------------------------------------------------------
// Kernel 3: fp16 HMMA GEMM  C[M,N] = X[M,K] * W[N,K]^T  (fp16 out)
// 128x128 tile, BK=64, 3-stage cp.async, 8 warps (2Mx4N), warp tile 64x32
// ---------------------------------------------------------------------------
__device__ __forceinline__ void issue_stage_loads(
    uint32_t sb, int buf, int c, int tid,
    const __half* A, const __half* B)
{
    const int k0 = c * BK;
    const uint32_t stage = sb + buf * STAGE_BYTES;
    #pragma unroll
    for (int it = 0; it < 4; it++) {
        int idx = tid + it * 256;        // 0..1023
        int r = idx >> 3;                // 0..127
        int cb = idx & 7;                // 16B chunk within 128B row
        cp_async16(stage + r * ROWB + cb * 16,
                   A + (size_t)r * NDIM + k0 + cb * 8);
    }
    #pragma unroll
    for (int it = 0; it < 4; it++) {
        int idx = tid + it * 256;
        int r = idx >> 3;
        int cb = idx & 7;
        cp_async16(stage + ARR_BYTES + r * ROWB + cb * 16,
                   B + (size_t)r * NDIM + k0 + cb * 8);
    }
}

__global__ __launch_bounds__(256, 2)
void k_gemm_hmma()
{
    extern __shared__ char smem[];
    const uint32_t sb = smem_u32(smem);
    const int tid = threadIdx.x;
    const int wid = tid >> 5, lane = tid & 31;
    const int wm = wid & 1;          // 0..1 (M)
    const int wn = wid >> 1;         // 0..3 (N)

    const __half* A = g_X + (size_t)blockIdx.y * BM * NDIM;
    const __half* B = g_W + (size_t)blockIdx.x * BN * NDIM;

    float acc[4][4][4];
    #pragma unroll
    for (int i = 0; i < 4; i++)
        #pragma unroll
        for (int j = 0; j < 4; j++)
            #pragma unroll
            for (int e = 0; e < 4; e++) acc[i][j][e] = 0.f;

    issue_stage_loads(sb, 0, 0, tid, A, B); cp_commit();
    issue_stage_loads(sb, 1, 1, tid, A, B); cp_commit();

    const int lrow = lane & 15;
    const int lkb  = (lane >> 4) * 16;

    for (int c = 0; c < NKCHUNK; c++) {
        cp_wait<1>();
        __syncthreads();

        if (c + 2 < NKCHUNK) {
            int nb = (c + 2) % STAGES;
            issue_stage_loads(sb, nb, c + 2, tid, A, B);
        }
        cp_commit();

        const uint32_t stage = sb + (c % STAGES) * STAGE_BYTES;
        const uint32_t sA = stage;
        const uint32_t sB = stage + ARR_BYTES;

        #pragma unroll
        for (int kk = 0; kk < 4; kk++) {
            const int kb = kk * 32 + lkb;
            uint32_t af[4][4], bf[2][4];
            #pragma unroll
            for (int i = 0; i < 4; i++)
                ldm_x4(af[i], sA + (wm * 64 + i * 16 + lrow) * ROWB + kb);
            #pragma unroll
            for (int bt = 0; bt < 2; bt++)
                ldm_x4(bf[bt], sB + (wn * 32 + bt * 16 + lrow) * ROWB + kb);
            #pragma unroll
            for (int i = 0; i < 4; i++)
                #pragma unroll
                for (int j = 0; j < 4; j++) {
                    const int bt = j >> 1, odd = j & 1;
                    mma_f16(acc[i][j], af[i], bf[bt][odd], bf[bt][odd + 2]);
                }
        }
    }

    // Epilogue: fp16 stores into g_C
    const int crow0 = blockIdx.y * BM + wm * 64 + (lane >> 2);
    const int ccol0 = blockIdx.x * BN + wn * 32 + (lane & 3) * 2;
    #pragma unroll
    for (int i = 0; i < 4; i++)
        #pragma unroll
        for (int j = 0; j < 4; j++) {
            __half2 h0 = __floats2half2_rn(acc[i][j][0], acc[i][j][1]);
            __half2 h1 = __floats2half2_rn(acc[i][j][2], acc[i][j][3]);
            *(__half2*)(g_C + (size_t)(crow0 + i * 16)     * MDIM + ccol0 + j * 8) = h0;
            *(__half2*)(g_C + (size_t)(crow0 + i * 16 + 8) * MDIM + ccol0 + j * 8) = h1;
        }
}

// ---------------------------------------------------------------------------
// Kernel 4: out = fwht(g_C)/64 * SV  (radix-8, fp16 in, fp32 out)
// ---------------------------------------------------------------------------
__global__ __launch_bounds__(512)
void k_fwht_out(float* __restrict__ out,
                const float* __restrict__ SV)
{
    __shared__ float s[FW_SMEM];
    const int row = blockIdx.x;
    const int t = threadIdx.x;

    {
        uint4 u = ((const uint4*)(g_C + (size_t)row * MDIM))[t];
        float2 f0 = __half22float2(*(__half2*)&u.x);
        float2 f1 = __half22float2(*(__half2*)&u.y);
        float2 f2 = __half22float2(*(__half2*)&u.z);
        float2 f3 = __half22float2(*(__half2*)&u.w);
        float v[8] = {f0.x, f0.y, f1.x, f1.y, f2.x, f2.y, f3.x, f3.y};
        radix8(v);
        #pragma unroll
        for (int j = 0; j < 8; j++) s[SKEW(8 * t + j)] = v[j];
    }
    __syncthreads();

    #pragma unroll
    for (int lh = 3; lh <= 9; lh += 3) {
        const int h = 1 << lh;
        const int i = ((t >> lh) << (lh + 3)) | (t & (h - 1));
        float v[8];
        #pragma unroll
        for (int k = 0; k < 8; k++) v[k] = s[SKEW(i + k * h)];
        radix8(v);
        #pragma unroll
        for (int k = 0; k < 8; k++) s[SKEW(i + k * h)] = v[k];
        __syncthreads();
    }

    {
        const float4* sv4 = (const float4*)SV;
        float4 sa = sv4[2 * t], sb = sv4[2 * t + 1];
        float4 o0, o1;
        o0.x = s[SKEW(8 * t + 0)] * 0.015625f * sa.x;
        o0.y = s[SKEW(8 * t + 1)] * 0.015625f * sa.y;
        o0.z = s[SKEW(8 * t + 2)] * 0.015625f * sa.z;
        o0.w = s[SKEW(8 * t + 3)] * 0.015625f * sa.w;
        o1.x = s[SKEW(8 * t + 4)] * 0.015625f * sb.x;
        o1.y = s[SKEW(8 * t + 5)] * 0.015625f * sb.y;
        o1.z = s[SKEW(8 * t + 6)] * 0.015625f * sb.z;
        o1.w = s[SKEW(8 * t + 7)] * 0.015625f * sb.w;
        float4* out4 = (float4*)(out + (size_t)row * MDIM);
        out4[2 * t]     = o0;
        out4[2 * t + 1] = o1;
    }
}

// ---------------------------------------------------------------------------
extern "C" void kernel_launch(void* const* d_in, const int* in_sizes, int n_in,
                              void* d_out, int out_size)
{
    const float* input = (const float*)d_in[0];
    const float* SU    = (const float*)d_in[1];
    const float* SV    = (const float*)d_in[2];
    const float* grid  = (const float*)d_in[3];
    const int*   qidx  = (const int*)  d_in[4];
    float* out = (float*)d_out;
    (void)in_sizes; (void)n_in; (void)out_size;

    cudaFuncSetAttribute(k_gemm_hmma, cudaFuncAttributeMaxDynamicSharedMemorySize, SMEM_TOTAL);

    k_dequant<<<NIDX / 256, 256>>>(grid, qidx);
    k_fwht_in<<<MROWS, 512>>>(input, SU);
    {
        dim3 gd(MDIM / BN, MROWS / BM);
        k_gemm_hmma<<<gd, 256, SMEM_TOTAL>>>();
    }
    k_fwht_out<<<MROWS, 512>>>(out, SV);
}